// round 2
// baseline (speedup 1.0000x reference)
#include <cuda_runtime.h>
#include <math.h>

#define N_INST 32768
#define D      2048
#define DP     512
#define CLASSES 4

// ---------------- scratch (no allocations allowed) ----------------
__device__ float g_S[N_INST];        // logits
__device__ float g_A[N_INST];        // softmax weights
__device__ float g_tp[64][D];        // pooling partials (64 row-stripes)
__device__ float g_t[D];             // pooled vector

// ---------------- kernel 1: S[i] = sum_j w_j * tanh(U_j . V_i) ----------------
// Block: 64 instances (i), loops over 8 j-tiles of 64. 256 threads = 16(tx,i) x 16(ty,j),
// each thread a 4x4 micro-tile. k-major smem tiles for vectorized LDS.128.
#define BN  64
#define BJ  64
#define BK  16
#define PAD 68   // padded row (floats), keeps 16B alignment (68*4=272B)

__global__ __launch_bounds__(256) void k_scores(const float* __restrict__ V,
                                                const float* __restrict__ U,
                                                const float* __restrict__ Wm)
{
    __shared__ float Us[BK][PAD];
    __shared__ float Vs[BK][PAD];
    __shared__ float Wsh[DP];
    __shared__ float red[16][BN];

    const int tid = threadIdx.x;
    const int tx  = tid & 15;   // i group
    const int ty  = tid >> 4;   // j group
    const int ibase = blockIdx.x * BN;

    for (int j = tid; j < DP; j += 256) Wsh[j] = Wm[j];

    // loader mapping: 4 threads per tile-row, one float4 each
    const int lr = tid >> 2;          // 0..63 row within tile
    const int lq = (tid & 3) * 4;     // k quad offset 0/4/8/12

    const float* Vrow = V + (size_t)(ibase + lr) * D + lq;

    float part0 = 0.f, part1 = 0.f, part2 = 0.f, part3 = 0.f;

    for (int jb = 0; jb < DP / BJ; ++jb) {
        float acc[4][4];
        #pragma unroll
        for (int a = 0; a < 4; ++a)
            #pragma unroll
            for (int b = 0; b < 4; ++b) acc[a][b] = 0.f;

        const float* Urow = U + (size_t)(jb * BJ + lr) * D + lq;

        for (int k0 = 0; k0 < D; k0 += BK) {
            float4 u4 = *(const float4*)(Urow + k0);
            float4 v4 = *(const float4*)(Vrow + k0);
            __syncthreads();               // protect previous iter reads
            Us[lq + 0][lr] = u4.x; Us[lq + 1][lr] = u4.y;
            Us[lq + 2][lr] = u4.z; Us[lq + 3][lr] = u4.w;
            Vs[lq + 0][lr] = v4.x; Vs[lq + 1][lr] = v4.y;
            Vs[lq + 2][lr] = v4.z; Vs[lq + 3][lr] = v4.w;
            __syncthreads();

            #pragma unroll
            for (int kk = 0; kk < BK; ++kk) {
                float4 a4 = *(const float4*)&Us[kk][ty * 4];
                float4 b4 = *(const float4*)&Vs[kk][tx * 4];
                acc[0][0] += a4.x * b4.x; acc[0][1] += a4.x * b4.y;
                acc[0][2] += a4.x * b4.z; acc[0][3] += a4.x * b4.w;
                acc[1][0] += a4.y * b4.x; acc[1][1] += a4.y * b4.y;
                acc[1][2] += a4.y * b4.z; acc[1][3] += a4.y * b4.w;
                acc[2][0] += a4.z * b4.x; acc[2][1] += a4.z * b4.y;
                acc[2][2] += a4.z * b4.z; acc[2][3] += a4.z * b4.w;
                acc[3][0] += a4.w * b4.x; acc[3][1] += a4.w * b4.y;
                acc[3][2] += a4.w * b4.z; acc[3][3] += a4.w * b4.w;
            }
        }

        // fold this j-tile into per-instance partials: w_j * tanh(y)
        #pragma unroll
        for (int jj = 0; jj < 4; ++jj) {
            float wj = Wsh[jb * BJ + ty * 4 + jj];
            part0 += wj * tanhf(acc[jj][0]);
            part1 += wj * tanhf(acc[jj][1]);
            part2 += wj * tanhf(acc[jj][2]);
            part3 += wj * tanhf(acc[jj][3]);
        }
    }

    __syncthreads();
    red[ty][tx * 4 + 0] = part0;
    red[ty][tx * 4 + 1] = part1;
    red[ty][tx * 4 + 2] = part2;
    red[ty][tx * 4 + 3] = part3;
    __syncthreads();

    if (tid < BN) {
        float s = 0.f;
        #pragma unroll
        for (int r = 0; r < 16; ++r) s += red[r][tid];
        g_S[ibase + tid] = s;
    }
}

// ---------------- kernel 2: softmax over 32768 logits (one block) ----------------
__global__ __launch_bounds__(1024) void k_softmax()
{
    __shared__ float sm[1024];
    const int tid = threadIdx.x;

    float m = -INFINITY;
    for (int i = tid; i < N_INST; i += 1024) m = fmaxf(m, g_S[i]);
    sm[tid] = m; __syncthreads();
    for (int s = 512; s > 0; s >>= 1) {
        if (tid < s) sm[tid] = fmaxf(sm[tid], sm[tid + s]);
        __syncthreads();
    }
    const float mx = sm[0];
    __syncthreads();

    float z = 0.f;
    for (int i = tid; i < N_INST; i += 1024) z += expf(g_S[i] - mx);
    sm[tid] = z; __syncthreads();
    for (int s = 512; s > 0; s >>= 1) {
        if (tid < s) sm[tid] += sm[tid + s];
        __syncthreads();
    }
    const float inv = 1.0f / sm[0];

    for (int i = tid; i < N_INST; i += 1024)
        g_A[i] = expf(g_S[i] - mx) * inv;
}

// ---------------- kernel 3: t_partial[stripe][k] = sum_{i in stripe} a_i * V[i][k] ----
// grid (2, 64): x = 1024-column half, y = 512-row stripe. No atomics -> deterministic.
__global__ __launch_bounds__(256) void k_pool(const float* __restrict__ V)
{
    __shared__ float ash[512];
    const int tid = threadIdx.x;
    const int k   = blockIdx.x * 1024 + tid * 4;
    const int i0  = blockIdx.y * 512;

    for (int i = tid; i < 512; i += 256) ash[i] = g_A[i0 + i];
    __syncthreads();

    float4 acc = make_float4(0.f, 0.f, 0.f, 0.f);
    #pragma unroll 4
    for (int i = 0; i < 512; ++i) {
        float  a = ash[i];
        float4 v = *(const float4*)(V + (size_t)(i0 + i) * D + k);
        acc.x += a * v.x; acc.y += a * v.y;
        acc.z += a * v.z; acc.w += a * v.w;
    }
    *(float4*)&g_tp[blockIdx.y][k] = acc;
}

__global__ void k_pool_reduce()
{
    const int k = blockIdx.x * blockDim.x + threadIdx.x;  // 2048 total
    float s = 0.f;
    #pragma unroll
    for (int r = 0; r < 64; ++r) s += g_tp[r][k];
    g_t[k] = s;
}

// ---------------- kernel 4: out[c] = W[c] . t ----------------
__global__ void k_final(const float* __restrict__ W, float* __restrict__ out)
{
    const int c    = threadIdx.y;   // 0..3
    const int lane = threadIdx.x;   // 0..31
    float s = 0.f;
    for (int k = lane; k < D; k += 32) s += W[c * D + k] * g_t[k];
    #pragma unroll
    for (int o = 16; o > 0; o >>= 1) s += __shfl_down_sync(0xffffffff, s, o);
    if (lane == 0) out[c] = s;
}

// ---------------- launcher ----------------
extern "C" void kernel_launch(void* const* d_in, const int* in_sizes, int n_in,
                              void* d_out, int out_size)
{
    const float* V  = (const float*)d_in[0];   // V_prime [32768, 2048]
    const float* U  = (const float*)d_in[1];   // U_t     [512, 2048]
    const float* Wm = (const float*)d_in[2];   // W_mta   [1, 512]
    const float* W  = (const float*)d_in[3];   // W       [4, 2048]
    float* out = (float*)d_out;

    k_scores<<<N_INST / BN, 256>>>(V, U, Wm);
    k_softmax<<<1, 1024>>>();
    k_pool<<<dim3(2, 64), 256>>>(V);
    k_pool_reduce<<<2, 1024>>>();
    k_final<<<1, dim3(32, 4)>>>(W, out);
}

// round 4
// speedup vs baseline: 2.8785x; 2.8785x over previous
#include <cuda_runtime.h>
#include <cuda_bf16.h>
#include <math.h>
#include <stdint.h>

#define N_INST 32768
#define D      2048
#define DP     512
#define CLASSES 4

#define TM 256            // instances per CTA
#define TN 128            // j per CTA
#define NSTAGE 4          // smem buffers (3 in flight)
#define STG 49152         // 32KB A + 16KB B per stage
#define NSTOT 96          // 32 k-tiles * 3 split terms

// ---------------- scratch (module-scope, no runtime allocation) ----------------
__device__ __align__(1024) uint8_t g_Vhi[(size_t)N_INST * D * 2];
__device__ __align__(1024) uint8_t g_Vlo[(size_t)N_INST * D * 2];
__device__ __align__(1024) uint8_t g_Uhi[DP * D * 2];
__device__ __align__(1024) uint8_t g_Ulo[DP * D * 2];
__device__ float g_Sp[4][N_INST];   // per-j-tile logit partials
__device__ float g_S[N_INST];
__device__ float g_A[N_INST];
__device__ float g_tp[64][D];
__device__ float g_t[D];

// ---------------- PTX helpers (all plain-sm_103 safe: sm_80-era features) ----------------
static __device__ __forceinline__ uint32_t smem_u32(const void* p) {
    uint32_t a;
    asm("{ .reg .u64 t; cvta.to.shared.u64 t, %1; cvt.u32.u64 %0, t; }" : "=r"(a) : "l"(p));
    return a;
}
static __device__ __forceinline__ void cp16(uint32_t dst, const void* src) {
    asm volatile("cp.async.cg.shared.global [%0], [%1], 16;" :: "r"(dst), "l"(src) : "memory");
}
static __device__ __forceinline__ void ldsm4(uint32_t* r, uint32_t addr) {
    asm volatile("ldmatrix.sync.aligned.m8n8.x4.shared.b16 {%0,%1,%2,%3}, [%4];"
                 : "=r"(r[0]), "=r"(r[1]), "=r"(r[2]), "=r"(r[3]) : "r"(addr));
}
static __device__ __forceinline__ void mma16816(float* d, const uint32_t* a, uint32_t b0, uint32_t b1) {
    asm volatile("mma.sync.aligned.m16n8k16.row.col.f32.bf16.bf16.f32 "
                 "{%0,%1,%2,%3}, {%4,%5,%6,%7}, {%8,%9}, {%0,%1,%2,%3};"
                 : "+f"(d[0]), "+f"(d[1]), "+f"(d[2]), "+f"(d[3])
                 : "r"(a[0]), "r"(a[1]), "r"(a[2]), "r"(a[3]), "r"(b0), "r"(b1));
}
static __device__ __forceinline__ uint32_t pack2bf(__nv_bfloat16 a, __nv_bfloat16 b) {
    __nv_bfloat162 t = __halves2bfloat162(a, b);
    return *(uint32_t*)&t;
}

// ---------------- pack kernels: fp32 -> (hi,lo) bf16, plain row-major ----------------
__global__ __launch_bounds__(256) void k_packV(const float* __restrict__ V) {
    uint32_t idx = blockIdx.x * 256 + threadIdx.x;   // 16,777,216 float4-quads
    float4 v = *(const float4*)(V + (size_t)idx * 4);
    __nv_bfloat16 h0 = __float2bfloat16(v.x), h1 = __float2bfloat16(v.y);
    __nv_bfloat16 h2 = __float2bfloat16(v.z), h3 = __float2bfloat16(v.w);
    __nv_bfloat16 l0 = __float2bfloat16(v.x - __bfloat162float(h0));
    __nv_bfloat16 l1 = __float2bfloat16(v.y - __bfloat162float(h1));
    __nv_bfloat16 l2 = __float2bfloat16(v.z - __bfloat162float(h2));
    __nv_bfloat16 l3 = __float2bfloat16(v.w - __bfloat162float(h3));
    ((uint2*)g_Vhi)[idx] = make_uint2(pack2bf(h0, h1), pack2bf(h2, h3));
    ((uint2*)g_Vlo)[idx] = make_uint2(pack2bf(l0, l1), pack2bf(l2, l3));
}
__global__ __launch_bounds__(256) void k_packU(const float* __restrict__ U) {
    uint32_t idx = blockIdx.x * 256 + threadIdx.x;   // 262,144 quads
    float4 v = *(const float4*)(U + (size_t)idx * 4);
    __nv_bfloat16 h0 = __float2bfloat16(v.x), h1 = __float2bfloat16(v.y);
    __nv_bfloat16 h2 = __float2bfloat16(v.z), h3 = __float2bfloat16(v.w);
    __nv_bfloat16 l0 = __float2bfloat16(v.x - __bfloat162float(h0));
    __nv_bfloat16 l1 = __float2bfloat16(v.y - __bfloat162float(h1));
    __nv_bfloat16 l2 = __float2bfloat16(v.z - __bfloat162float(h2));
    __nv_bfloat16 l3 = __float2bfloat16(v.w - __bfloat162float(h3));
    ((uint2*)g_Uhi)[idx] = make_uint2(pack2bf(h0, h1), pack2bf(h2, h3));
    ((uint2*)g_Ulo)[idx] = make_uint2(pack2bf(l0, l1), pack2bf(l2, l3));
}

// ---------------- main GEMM: C[256x128] tile, mma.sync bf16, fused w*tanh fold ----------------
// smem layout per stage: A[256 rows x 128B] (32KB) then B[128 rows x 128B] (16KB),
// xor-swizzled (bits[6:4] ^= row%8) for conflict-free ldmatrix.
#define SMEM_BYTES (NSTAGE * STG + 512 + 4096 + 1024)

__global__ __launch_bounds__(512, 1) void k_scores_tc(const float* __restrict__ Wm)
{
    extern __shared__ uint8_t dsm[];
    uint32_t raw = smem_u32(dsm);
    uint32_t sb  = (raw + 1023) & ~1023u;
    uint8_t* sp  = dsm + (sb - raw);
    float* Wsh   = (float*)(sp + NSTAGE * STG);
    float* part  = (float*)(sp + NSTAGE * STG + 512);   // [4][256]

    const int tid  = threadIdx.x;
    const int lane = tid & 31, wid = tid >> 5;
    const int wm = wid & 3, wn = wid >> 2;          // warp tile: rows wm*64, cols wn*32
    const int ibase = blockIdx.x * TM;
    const int jbase = blockIdx.y * TN;

    if (tid < TN) Wsh[tid] = Wm[jbase + tid];

    const size_t aoff = (size_t)ibase * (D * 2);
    const size_t boff = (size_t)jbase * (D * 2);
    const uint8_t* aT[3] = { g_Vhi + aoff, g_Vhi + aoff, g_Vlo + aoff };
    const uint8_t* bT[3] = { g_Uhi + boff, g_Ulo + boff, g_Uhi + boff };

    // cp.async loader constants (each thread: 4 A-chunks + 2 B-chunks of 16B)
    const uint32_t lrow   = tid >> 3;                       // 0..63
    const uint32_t lc16   = (tid & 7) * 16;
    const uint32_t ld_dst = lc16 ^ ((lrow & 7) << 4);       // swizzled col part

    // ldmatrix constants
    const uint32_t mask  = (lane & 7) << 4;
    const uint32_t aRow  = (wm * 64 + (lane & 15)) * 128;
    const uint32_t bRow  = (wn * 32 + (lane & 7) + ((lane >> 1) & 8)) * 128;
    const uint32_t kselA = (lane & 16);        // k-half select for A x4
    const uint32_t kselB = (lane & 8) << 1;    // k-half select for B x4

    float acc[4][4][4];
    #pragma unroll
    for (int a = 0; a < 4; ++a)
        #pragma unroll
        for (int b = 0; b < 4; ++b)
            #pragma unroll
            for (int c = 0; c < 4; ++c) acc[a][b][c] = 0.f;

    auto load_stage = [&](int s) {
        const int kt = s / 3, term = s % 3;   // per-kt order: hi*hi, hi*lo, lo*hi
        const int buf = s & (NSTAGE - 1);
        const uint8_t* as = aT[term] + (size_t)kt * 128;
        const uint8_t* bs = bT[term] + (size_t)kt * 128;
        const uint32_t dA = sb + buf * STG;
        const uint32_t dB = dA + 32768;
        #pragma unroll
        for (int q = 0; q < 4; ++q) {
            uint32_t row = lrow + q * 64;
            cp16(dA + row * 128 + ld_dst, as + (size_t)row * 4096 + lc16);
        }
        #pragma unroll
        for (int q = 0; q < 2; ++q) {
            uint32_t row = lrow + q * 64;
            cp16(dB + row * 128 + ld_dst, bs + (size_t)row * 4096 + lc16);
        }
        asm volatile("cp.async.commit_group;" ::: "memory");
    };

    load_stage(0); load_stage(1); load_stage(2);

    #pragma unroll 1
    for (int s = 0; s < NSTOT; ++s) {
        asm volatile("cp.async.wait_group 2;" ::: "memory");
        __syncthreads();
        const int buf = s & (NSTAGE - 1);
        const uint32_t smA = sb + buf * STG;
        const uint32_t smB = smA + 32768;

        #pragma unroll
        for (int kk = 0; kk < 4; ++kk) {
            const uint32_t kxA = (kk * 32 + kselA) ^ mask;
            const uint32_t kxB = (kk * 32 + kselB) ^ mask;
            uint32_t Af[4][4], Bf[2][4];
            #pragma unroll
            for (int mt = 0; mt < 4; ++mt) ldsm4(Af[mt], smA + aRow + mt * 2048 + kxA);
            #pragma unroll
            for (int p = 0; p < 2; ++p)   ldsm4(Bf[p],  smB + bRow + p  * 2048 + kxB);
            #pragma unroll
            for (int mt = 0; mt < 4; ++mt)
                #pragma unroll
                for (int nt = 0; nt < 4; ++nt) {
                    const uint32_t* B = Bf[nt >> 1];
                    mma16816(acc[mt][nt], Af[mt],
                             (nt & 1) ? B[2] : B[0], (nt & 1) ? B[3] : B[1]);
                }
        }
        if (s + 3 < NSTOT) load_stage(s + 3);
    }

    // ---- epilogue: s_part[i] = sum_{j in tile} w_j * tanh(c_ij) ----
    const int gr = lane >> 2;
    const int gc = (lane & 3) * 2;
    #pragma unroll
    for (int mt = 0; mt < 4; ++mt) {
        float l0 = 0.f, l1 = 0.f;
        #pragma unroll
        for (int nt = 0; nt < 4; ++nt) {
            int wi = wn * 32 + nt * 8 + gc;
            float w0 = Wsh[wi], w1 = Wsh[wi + 1];
            l0 += w0 * tanhf(acc[mt][nt][0]) + w1 * tanhf(acc[mt][nt][1]);
            l1 += w0 * tanhf(acc[mt][nt][2]) + w1 * tanhf(acc[mt][nt][3]);
        }
        l0 += __shfl_xor_sync(0xffffffffu, l0, 1);
        l0 += __shfl_xor_sync(0xffffffffu, l0, 2);
        l1 += __shfl_xor_sync(0xffffffffu, l1, 1);
        l1 += __shfl_xor_sync(0xffffffffu, l1, 2);
        if ((lane & 3) == 0) {
            part[wn * 256 + wm * 64 + mt * 16 + gr]     = l0;
            part[wn * 256 + wm * 64 + mt * 16 + 8 + gr] = l1;
        }
    }
    __syncthreads();
    if (tid < 256) {
        float sv = part[tid] + part[256 + tid] + part[512 + tid] + part[768 + tid];
        g_Sp[blockIdx.y][ibase + tid] = sv;
    }
}

// ---------------- softmax over 32768 logits (folds the 4 j-tile partials) ----------------
__global__ __launch_bounds__(1024) void k_softmax()
{
    __shared__ float sm[1024];
    const int tid = threadIdx.x;

    float m = -INFINITY;
    for (int i = tid; i < N_INST; i += 1024) {
        float s = g_Sp[0][i] + g_Sp[1][i] + g_Sp[2][i] + g_Sp[3][i];
        g_S[i] = s;
        m = fmaxf(m, s);
    }
    sm[tid] = m; __syncthreads();
    for (int s = 512; s > 0; s >>= 1) {
        if (tid < s) sm[tid] = fmaxf(sm[tid], sm[tid + s]);
        __syncthreads();
    }
    const float mx = sm[0];
    __syncthreads();

    float z = 0.f;
    for (int i = tid; i < N_INST; i += 1024) z += expf(g_S[i] - mx);
    sm[tid] = z; __syncthreads();
    for (int s = 512; s > 0; s >>= 1) {
        if (tid < s) sm[tid] += sm[tid + s];
        __syncthreads();
    }
    const float inv = 1.0f / sm[0];

    for (int i = tid; i < N_INST; i += 1024)
        g_A[i] = expf(g_S[i] - mx) * inv;
}

// ---------------- weighted pooling (deterministic two-stage) ----------------
__global__ __launch_bounds__(256) void k_pool(const float* __restrict__ V)
{
    __shared__ float ash[512];
    const int tid = threadIdx.x;
    const int k   = blockIdx.x * 1024 + tid * 4;
    const int i0  = blockIdx.y * 512;

    for (int i = tid; i < 512; i += 256) ash[i] = g_A[i0 + i];
    __syncthreads();

    float4 acc = make_float4(0.f, 0.f, 0.f, 0.f);
    #pragma unroll 4
    for (int i = 0; i < 512; ++i) {
        float  a = ash[i];
        float4 v = *(const float4*)(V + (size_t)(i0 + i) * D + k);
        acc.x += a * v.x; acc.y += a * v.y;
        acc.z += a * v.z; acc.w += a * v.w;
    }
    *(float4*)&g_tp[blockIdx.y][k] = acc;
}

__global__ void k_pool_reduce()
{
    const int k = blockIdx.x * blockDim.x + threadIdx.x;
    float s = 0.f;
    #pragma unroll
    for (int r = 0; r < 64; ++r) s += g_tp[r][k];
    g_t[k] = s;
}

// ---------------- final linear ----------------
__global__ void k_final(const float* __restrict__ W, float* __restrict__ out)
{
    const int c    = threadIdx.y;
    const int lane = threadIdx.x;
    float s = 0.f;
    for (int k = lane; k < D; k += 32) s += W[c * D + k] * g_t[k];
    #pragma unroll
    for (int o = 16; o > 0; o >>= 1) s += __shfl_down_sync(0xffffffff, s, o);
    if (lane == 0) out[c] = s;
}

// ---------------- launcher ----------------
extern "C" void kernel_launch(void* const* d_in, const int* in_sizes, int n_in,
                              void* d_out, int out_size)
{
    const float* V  = (const float*)d_in[0];   // V_prime [32768, 2048]
    const float* U  = (const float*)d_in[1];   // U_t     [512, 2048]
    const float* Wm = (const float*)d_in[2];   // W_mta   [1, 512]
    const float* W  = (const float*)d_in[3];   // W       [4, 2048]
    float* out = (float*)d_out;

    cudaFuncSetAttribute(k_scores_tc, cudaFuncAttributeMaxDynamicSharedMemorySize, SMEM_BYTES);

    k_packU<<<1024, 256>>>(U);
    k_packV<<<65536, 256>>>(V);
    k_scores_tc<<<dim3(128, 4), 512, SMEM_BYTES>>>(Wm);
    k_softmax<<<1, 1024>>>();
    k_pool<<<dim3(2, 64), 256>>>(V);
    k_pool_reduce<<<2, 1024>>>();
    k_final<<<1, dim3(32, 4)>>>(W, out);
}